// round 7
// baseline (speedup 1.0000x reference)
#include <cuda_runtime.h>

#define ALPHA 0.2f
#define B_   8
#define G_   8
#define V_   1024
#define FIN_ 64
#define FOUT_ 64
#define C_   512            // G_*FOUT_
#define OUTW_ 60            // FOUT_-4
#define OUTC_ 120           // 2*OUTW_

typedef unsigned long long ull;

// ---------------- scratch (device globals; no allocation) ----------------
__device__ __align__(16) float    g_Wh[B_*V_*C_];        // [b][v][c] leaky(Wh)
__device__ float                  g_Spart[B_*16*C_];     // partial col sums per v-tile
__device__ float                  g_S[B_*C_];            // col sums of leaky(Wh)
__device__ unsigned               g_rowmask[B_*V_*32];   // bit j set <=> a[b,i,j]==0
__device__ int                    g_zcol[B_*V_];         // zero count per column v
__device__ __align__(16) float    g_featin[B_*G_*V_*FOUT_];
__device__ __align__(16) float    g_featout[B_*G_*V_*FOUT_];

__device__ __forceinline__ float lrelu(float x) { return x >= 0.f ? x : ALPHA * x; }

// ---- packed fp32x2 helpers ----
__device__ __forceinline__ ull pack2(float x, float y) {
    ull r;
    asm("mov.b64 %0, {%1, %2};" : "=l"(r) : "f"(x), "f"(y));
    return r;
}
__device__ __forceinline__ ull bcast2(float x) {
    ull r;
    asm("mov.b64 %0, {%1, %1};" : "=l"(r) : "f"(x));
    return r;
}
__device__ __forceinline__ ull fma2(ull a, ull b, ull c) {
    ull d;
    asm("fma.rn.f32x2 %0, %1, %2, %3;" : "=l"(d) : "l"(a), "l"(b), "l"(c));
    return d;
}
__device__ __forceinline__ float2 unpack2(ull v) {
    float2 r;
    asm("mov.b64 {%0, %1}, %2;" : "=f"(r.x), "=f"(r.y) : "l"(v));
    return r;
}

// ---------------- K0: zero the column-zero counters ----------------
__global__ void k_zero() {
    int t = blockIdx.x * blockDim.x + threadIdx.x;
    if (t < B_ * V_) g_zcol[t] = 0;
}

// ---------------- K2: adj scan -> zero-edge bitmask + column zero counts ------
__global__ void __launch_bounds__(256) k_adj(const int* __restrict__ adj) {
    int i = blockIdx.x, b = blockIdx.y;
    __shared__ unsigned mask[32];
    int t = threadIdx.x;
    if (t < 32) mask[t] = 0u;
    __syncthreads();

    const int4* p = (const int4*)(adj + (size_t)b * G_ * V_ * V_ + (size_t)i * V_);
    int4 acc = p[t];
#pragma unroll
    for (int g = 1; g < G_; g++) {
        int4 v = p[(size_t)g * (V_ * (V_ / 4)) + t];
        acc.x |= v.x; acc.y |= v.y; acc.z |= v.z; acc.w |= v.w;
    }
    unsigned nib = (unsigned)(acc.x == 0) | ((unsigned)(acc.y == 0) << 1) |
                   ((unsigned)(acc.z == 0) << 2) | ((unsigned)(acc.w == 0) << 3);
    if (nib) {
        atomicOr(&mask[t >> 3], nib << ((t & 7) * 4));
        int jb = b * V_ + 4 * t;
        if (acc.x == 0) atomicAdd(&g_zcol[jb + 0], 1);
        if (acc.y == 0) atomicAdd(&g_zcol[jb + 1], 1);
        if (acc.z == 0) atomicAdd(&g_zcol[jb + 2], 1);
        if (acc.w == 0) atomicAdd(&g_zcol[jb + 3], 1);
    }
    __syncthreads();
    if (t < 32) g_rowmask[((size_t)b * V_ + i) * 32 + t] = mask[t];
}

// ---------------- K1: Wh = leaky(h @ W) per (b,g); also partial column sums ----
__global__ void __launch_bounds__(256) k_wh(const float* __restrict__ h,
                                            const float* __restrict__ W) {
    __shared__ __align__(16) float sW[64 * 64];   // [i][o]
    __shared__ __align__(16) float sH[64 * 64];   // [v][i]
    __shared__ float red[64 * 17];

    int t = threadIdx.x;
    int vt = blockIdx.x, g = blockIdx.y, b = blockIdx.z;

    const float4* wp = (const float4*)(W + (size_t)g * 4096);
    const float4* hp = (const float4*)(h + (((size_t)b * G_ + g) * V_ + (size_t)vt * 64) * 64);
    float4* sw4 = (float4*)sW;
    float4* sh4 = (float4*)sH;
#pragma unroll
    for (int q = t; q < 1024; q += 256) { sw4[q] = wp[q]; sh4[q] = hp[q]; }
    __syncthreads();

    int tx = t & 15, ty = t >> 4;
    int o0 = tx * 4, r0 = ty * 4;
    float acc[4][4] = {};
#pragma unroll 4
    for (int i = 0; i < 64; i++) {
        float4 bb = *(const float4*)(sW + i * 64 + o0);
#pragma unroll
        for (int r = 0; r < 4; r++) {
            float a = sH[(r0 + r) * 64 + i];
            acc[r][0] += a * bb.x; acc[r][1] += a * bb.y;
            acc[r][2] += a * bb.z; acc[r][3] += a * bb.w;
        }
    }

    float cs[4] = {0.f, 0.f, 0.f, 0.f};
#pragma unroll
    for (int r = 0; r < 4; r++) {
        float4 v;
        v.x = lrelu(acc[r][0]); v.y = lrelu(acc[r][1]);
        v.z = lrelu(acc[r][2]); v.w = lrelu(acc[r][3]);
        size_t row = (size_t)b * V_ + vt * 64 + r0 + r;
        *(float4*)(g_Wh + row * C_ + g * 64 + o0) = v;
        cs[0] += v.x; cs[1] += v.y; cs[2] += v.z; cs[3] += v.w;
    }
    __syncthreads();
#pragma unroll
    for (int j = 0; j < 4; j++) red[(o0 + j) * 17 + ty] = cs[j];
    __syncthreads();
    if (t < 64) {
        float s = 0.f;
#pragma unroll
        for (int k = 0; k < 16; k++) s += red[t * 17 + k];
        g_Spart[((size_t)b * 16 + vt) * C_ + g * 64 + t] = s;
    }
}

// ---------------- K1b: reduce partial sums -> S (64 blocks: latency) ----------
__global__ void k_sreduce() {
    int b = blockIdx.x >> 3;
    int c = (blockIdx.x & 7) * 64 + threadIdx.x;
    float s = 0.f;
#pragma unroll
    for (int vt = 0; vt < 16; vt++) s += g_Spart[((size_t)b * 16 + vt) * C_ + c];
    g_S[b * C_ + c] = s;
}

// ---------------- K3: assemble feature_in / feature_out planes ----------------
__global__ void __launch_bounds__(512) k_feat() {
    int i = blockIdx.x, b = blockIdx.y;
    int c = threadIdx.x;
    __shared__ short jlist[64];
    __shared__ int njs;
    __shared__ float sdeg;

    if (c == 0) sdeg = (float)(V_ - g_zcol[b * V_ + i]) * (1.0f / V_);
    if (c < 32) {
        unsigned mw = g_rowmask[((size_t)b * V_ + i) * 32 + c];
        int cnt = __popc(mw);
        int pre = cnt;
#pragma unroll
        for (int d = 1; d < 32; d <<= 1) {
            int v = __shfl_up_sync(0xffffffffu, pre, d);
            if (c >= d) pre += v;
        }
        int excl = pre - cnt;
        if (c == 31) njs = pre;
        while (mw) {
            int p = __ffs(mw) - 1;
            mw &= mw - 1;
            jlist[excl++] = (short)(c * 32 + p);
        }
    }
    __syncthreads();

    float S = g_S[b * C_ + c];
    float corr = 0.f;
    int n = njs;
    const float* whb = g_Wh + (size_t)b * V_ * C_ + c;
#pragma unroll 1
    for (int k = 0; k < n; k += 4) {
        float v0 = whb[(size_t)jlist[k] * C_];
        float v1 = (k + 1 < n) ? whb[(size_t)jlist[k + 1] * C_] : 0.f;
        float v2 = (k + 2 < n) ? whb[(size_t)jlist[k + 2] * C_] : 0.f;
        float v3 = (k + 3 < n) ? whb[(size_t)jlist[k + 3] * C_] : 0.f;
        corr += (v0 + v1) + (v2 + v3);
    }
    float fout = lrelu((S - corr) * (1.0f / V_));
    float fin  = lrelu(sdeg * whb[(size_t)i * C_]);

    int g = c >> 6, o = c & 63;
    size_t oidx = (((size_t)b * G_ + g) * V_ + i) * FOUT_ + o;
    g_featin[oidx]  = fin;
    g_featout[oidx] = fout;
}

// ---------------- K4: 5x5 conv (R2-proven), f32x2 output-channel pairs --------
__global__ void __launch_bounds__(512) k_conv(const float* __restrict__ cw1,
                                              const float* __restrict__ cb1,
                                              const float* __restrict__ cw2,
                                              const float* __restrict__ cb2,
                                              float* __restrict__ out) {
    int which = blockIdx.z;
    int b = blockIdx.y;
    int r0 = blockIdx.x * 16;

    __shared__ __align__(16) float sin_[8][20][64];    // [cin][row][col], 40 KB
    __shared__ __align__(8) float2 swt2[4 * 8 * 25];   // [gg][cin][tap] -> (wt_g0, wt_g1)
    __shared__ float2 sb2[4];

    const float* feat = which ? g_featout : g_featin;
    const float* cw = which ? cw2 : cw1;
    const float* cb = which ? cb2 : cb1;

    int t = threadIdx.x;
    for (int q = t; q < 800; q += 512) {
        int gg = q / 200;
        int rem = q - gg * 200;      // cin*25 + tap
        swt2[q] = make_float2(cw[(2 * gg) * 200 + rem], cw[(2 * gg + 1) * 200 + rem]);
    }
    if (t < 4) sb2[t] = make_float2(cb[2 * t], cb[2 * t + 1]);

#pragma unroll
    for (int q = t; q < 2560; q += 512) {
        int cin = q / 320;
        int rem = q - cin * 320;
        int row = rem >> 4;
        int o4  = rem & 15;
        int v = r0 - 2 + row;
        float4 val = make_float4(0.f, 0.f, 0.f, 0.f);
        if (v >= 0 && v < V_)
            val = *(const float4*)(feat + (((size_t)b * G_ + cin) * V_ + v) * FOUT_ + o4 * 4);
        *(float4*)(&sin_[cin][row][o4 * 4]) = val;
    }
    __syncthreads();

    int cg = t & 15, rg = (t >> 4) & 7, gg = t >> 7;
    if (cg < 15) {
        int w0 = cg * 4;
        int lr = rg * 2;

        ull bias = pack2(sb2[gg].x, sb2[gg].y);
        ull acc[2][4];
#pragma unroll
        for (int r = 0; r < 2; r++)
#pragma unroll
            for (int c = 0; c < 4; c++) acc[r][c] = bias;

        const float2* wp = &swt2[gg * 200];

#pragma unroll 1
        for (int cin = 0; cin < 8; cin++) {
#pragma unroll
            for (int kh = 0; kh < 5; kh++) {
                ull in2[2][8];
#pragma unroll
                for (int rr = 0; rr < 2; rr++) {
                    float4 a4 = *(const float4*)(&sin_[cin][lr + kh + rr][w0]);
                    float4 b4 = *(const float4*)(&sin_[cin][lr + kh + rr][w0 + 4]);
                    in2[rr][0] = bcast2(a4.x); in2[rr][1] = bcast2(a4.y);
                    in2[rr][2] = bcast2(a4.z); in2[rr][3] = bcast2(a4.w);
                    in2[rr][4] = bcast2(b4.x); in2[rr][5] = bcast2(b4.y);
                    in2[rr][6] = bcast2(b4.z); in2[rr][7] = bcast2(b4.w);
                }
#pragma unroll
                for (int kw = 0; kw < 5; kw++) {
                    float2 w2 = wp[cin * 25 + kh * 5 + kw];
                    ull wt = pack2(w2.x, w2.y);
#pragma unroll
                    for (int r = 0; r < 2; r++) {
#pragma unroll
                        for (int c = 0; c < 4; c++)
                            acc[r][c] = fma2(in2[r][kw + c], wt, acc[r][c]);
                    }
                }
            }
        }

#pragma unroll
        for (int r = 0; r < 2; r++) {
            float2 u0 = unpack2(acc[r][0]);
            float2 u1 = unpack2(acc[r][1]);
            float2 u2 = unpack2(acc[r][2]);
            float2 u3 = unpack2(acc[r][3]);
            int v = r0 + lr + r;
            size_t base0 = (((size_t)b * G_ + (2 * gg)) * V_ + v) * OUTC_ + which * OUTW_ + w0;
            size_t base1 = (((size_t)b * G_ + (2 * gg + 1)) * V_ + v) * OUTC_ + which * OUTW_ + w0;
            *(float4*)(out + base0) = make_float4(u0.x, u1.x, u2.x, u3.x);
            *(float4*)(out + base1) = make_float4(u0.y, u1.y, u2.y, u3.y);
        }
    }
}

// ---------------- launch: fork adj (DRAM) ∥ wh+sreduce (FMA) ----------------
extern "C" void kernel_launch(void* const* d_in, const int* in_sizes, int n_in,
                              void* d_out, int out_size) {
    const float* h       = (const float*)d_in[0];
    const int*   adj     = (const int*)d_in[1];
    const float* W       = (const float*)d_in[2];
    const float* conv1_w = (const float*)d_in[3];
    const float* conv1_b = (const float*)d_in[4];
    const float* conv2_w = (const float*)d_in[5];
    const float* conv2_b = (const float*)d_in[6];
    float* out = (float*)d_out;

    // created once on the (uncaptured) correctness call; reused under capture
    static cudaStream_t s1 = nullptr;
    static cudaEvent_t ev0 = nullptr, ev1 = nullptr;
    if (s1 == nullptr) {
        cudaStreamCreateWithFlags(&s1, cudaStreamNonBlocking);
        cudaEventCreateWithFlags(&ev0, cudaEventDisableTiming);
        cudaEventCreateWithFlags(&ev1, cudaEventDisableTiming);
    }

    k_zero<<<8, 1024>>>();                                  // legacy stream
    cudaEventRecord(ev0, 0);
    cudaStreamWaitEvent(s1, ev0, 0);

    k_adj<<<dim3(V_, B_), 256>>>(adj);                      // legacy: DRAM-bound
    k_wh<<<dim3(16, G_, B_), 256, 0, s1>>>(h, W);           // s1: FMA-bound
    k_sreduce<<<64, 64, 0, s1>>>();                         // s1

    cudaEventRecord(ev1, s1);
    cudaStreamWaitEvent(0, ev1, 0);                         // join

    k_feat<<<dim3(V_, B_), 512>>>();
    k_conv<<<dim3(V_ / 16, B_, 2), 512>>>(conv1_w, conv1_b, conv2_w, conv2_b, out);
}